// round 15
// baseline (speedup 1.0000x reference)
#include <cuda_runtime.h>

// LM pose solver: B=4096 batches, N=512 points, DOF=4 (tx,ty,tz,yaw).
// One 32-thread CTA (single warp) per batch; 8 packed f32x2 point-pairs per
// lane. Pinhole-K fast path (exact zeros -> bit-identical to general form).
// This round: launch_bounds 17 -> 21 CTAs/SM (regs=96 measured; regfile
// allows 21, smem 10KB allows 22 -- the old bound was the binding limit),
// plus pair-packed butterfly (7 u64 reductions: 70 SHFL + 35 f2add instead
// of 70 SHFL + 70 FADD; per-component arithmetic identical).

#define NPTS     512
#define NPAIRS_T 256                     // total float2 pairs
#define THREADS  32
#define NPAIRS   (NPAIRS_T / THREADS)    // 8 pairs per lane
#define NUM_ITER 10

typedef unsigned long long u64;

__device__ __forceinline__ u64 pk2(float lo, float hi) {
    u64 r; asm("mov.b64 %0,{%1,%2};" : "=l"(r) : "f"(lo), "f"(hi)); return r;
}
__device__ __forceinline__ u64 pkb(float s) { return pk2(s, s); }
__device__ __forceinline__ void unpk2(u64 a, float& lo, float& hi) {
    asm("mov.b64 {%0,%1},%2;" : "=f"(lo), "=f"(hi) : "l"(a));
}
__device__ __forceinline__ u64 f2fma(u64 a, u64 b, u64 c) {
    u64 d; asm("fma.rn.f32x2 %0,%1,%2,%3;" : "=l"(d) : "l"(a), "l"(b), "l"(c)); return d;
}
__device__ __forceinline__ u64 f2mul(u64 a, u64 b) {
    u64 d; asm("mul.rn.f32x2 %0,%1,%2;" : "=l"(d) : "l"(a), "l"(b)); return d;
}
__device__ __forceinline__ u64 f2add(u64 a, u64 b) {
    u64 d; asm("add.rn.f32x2 %0,%1,%2;" : "=l"(d) : "l"(a), "l"(b)); return d;
}
__device__ __forceinline__ float frcp(float x) {
    float r; asm("rcp.approx.f32 %0, %1;" : "=f"(r) : "f"(x)); return r;
}
// warp butterfly sum (all lanes get total)
__device__ __forceinline__ float wsum(float x) {
#pragma unroll
    for (int o = 16; o > 0; o >>= 1)
        x += __shfl_xor_sync(0xffffffffu, x, o);
    return x;
}

// fp32 Gaussian elimination, no pivoting (A is SPD + LM damping).
// All reciprocals via rcp.approx (error ~1ulp*few, far inside 1e-3 budget).
__device__ __forceinline__ void solve4f(float A[4][4], float bv[4], float x[4]) {
#pragma unroll
    for (int k = 0; k < 4; k++) {
        const float inv = frcp(A[k][k]);
#pragma unroll
        for (int i = 0; i < 4; i++) {
            if (i > k) {
                const float f = A[i][k] * inv;
#pragma unroll
                for (int j = 0; j < 4; j++)
                    if (j >= k) A[i][j] = fmaf(-f, A[k][j], A[i][j]);
                bv[i] = fmaf(-f, bv[k], bv[i]);
            }
        }
    }
#pragma unroll
    for (int k = 3; k >= 0; k--) {
        float s = bv[k];
#pragma unroll
        for (int j = 0; j < 4; j++)
            if (j > k) s = fmaf(-A[k][j], x[j], s);
        x[k] = s * frcp(A[k][k]);
    }
}

__global__ void __launch_bounds__(THREADS, 21) lm_kernel(
    const float* __restrict__ x3d,
    const float* __restrict__ x2d,
    const float* __restrict__ w2d,
    const float* __restrict__ pose_init,
    const float* __restrict__ cam,
    float* __restrict__ out,   // [4B pose | B cost | 4B pose_plus]
    int B)
{
    // pair-packed layout (10KB total): sA=(X0,X1,Y0,Y1), sB=(Z0,Z1,WU0,WU1),
    // sC=(WV0,WV1). x2d stays in global (L2-resident), read per pass.
    __shared__ float4 sA[NPAIRS_T], sB[NPAIRS_T];
    __shared__ float2 sC[NPAIRS_T];

    const int b   = blockIdx.x;
    const int tid = threadIdx.x;

    // ---- stage x3d / w2d into smem (one-time) ----
    const float2* __restrict__ xb = (const float2*)(x3d + (size_t)b * NPTS * 3);
    const float4* __restrict__ wb = (const float4*)(w2d + (size_t)b * NPTS * 2);
    const float4* __restrict__ ub = (const float4*)(x2d + (size_t)b * NPTS * 2);
    for (int j = tid; j < NPAIRS_T; j += THREADS) {
        // pair j = points (2j, 2j+1): x3d floats 6j..6j+5, 8B-aligned
        const float2 xa = xb[3*j+0];   // X0, Y0
        const float2 xc = xb[3*j+1];   // Z0, X1
        const float2 xd = xb[3*j+2];   // Y1, Z1
        const float4 w4 = wb[j];       // wu0, wv0, wu1, wv1
        sA[j] = make_float4(xa.x, xc.y, xa.y, xd.x);   // X0,X1,Y0,Y1
        sB[j] = make_float4(xc.x, xd.y, w4.x, w4.z);   // Z0,Z1,WU0,WU1
        sC[j] = make_float2(w4.y, w4.w);               // WV0,WV1
    }

    float Kr[9];
#pragma unroll
    for (int k = 0; k < 9; k++) Kr[k] = cam[(size_t)b * 9 + k];
    // Pinhole check: with exact zeros the specialized math is BIT-IDENTICAL
    // to the general formula (fmaf(x,0,y)==y exactly).
    const bool pin = (Kr[1] == 0.f) && (Kr[3] == 0.f) && (Kr[6] == 0.f) &&
                     (Kr[7] == 0.f) && (Kr[8] == 1.f);

    float pose[4];
#pragma unroll
    for (int k = 0; k < 4; k++) pose[k] = pose_init[b * 4 + k];
    float jt[10], gr[4];
    float cst = 0.f, radius = 30.0f, dec = 2.0f;

    float cy = __cosf(pose[3]);
    float sy = __sinf(pose[3]);
    float tx = pose[0], ty = pose[1], tz = pose[2];

    __syncwarp();   // staging visible warp-wide

    float t[15];

    // One fused residual+jacobian reduction pass at (tx,ty,tz,cy,sy).
    // On exit every lane holds the batch-wide sums in t[0..14].
    auto do_pass = [&]() {
        if (pin) {
            const float fx = Kr[0], cx = Kr[2], fy = Kr[4], cyk = Kr[5];
            u64 A0 = 0, A2 = 0, A3 = 0, A4 = 0, A5 = 0, A6 = 0, A7 = 0,
                A8 = 0, A9 = 0, A10 = 0, A11 = 0, A12 = 0, A13 = 0, A14 = 0;
            const u64 TX = pkb(tx), TY = pkb(ty), TZ = pkb(tz), nTZ = pkb(-tz);
            const u64 CYr = pkb(cy), SYr = pkb(sy), nSY = pkb(-sy);
            const u64 FX = pkb(fx), CX = pkb(cx), FY = pkb(fy), CYK = pkb(cyk);
            const u64 M1 = pkb(-1.0f);
#pragma unroll
            for (int p = 0; p < NPAIRS; p++) {
                const int j = tid + p * THREADS;
                const float4 a4 = sA[j];
                const float4 b4 = sB[j];
                const float2 c2 = sC[j];
                const float4 q4 = ub[j];                // U0,V0,U1,V1 (global/L2)
                const u64 Px = pk2(a4.x, a4.y), Py = pk2(a4.z, a4.w);
                const u64 Pz = pk2(b4.x, b4.y), WU = pk2(b4.z, b4.w);
                const u64 WV = pk2(c2.x, c2.y);
                const u64 UU = pk2(q4.x, q4.z), VV = pk2(q4.y, q4.w);
                const u64 p0 = f2fma(CYr, Px, f2fma(SYr, Pz, TX));
                const u64 p1 = f2add(Py, TY);
                const u64 p2 = f2fma(nSY, Px, f2fma(CYr, Pz, TZ));
                const u64 av = f2add(p2, nTZ);          //  -s*X + c*Z
                const u64 bv = f2fma(p0, M1, TX);       // -(c*X + s*Z)
                const u64 ph0 = f2fma(FX, p0, f2mul(CX, p2));
                const u64 ph1 = f2fma(FY, p1, f2mul(CYK, p2));
                float z0, z1; unpk2(p2, z0, z1);        // ph2 == p2 (K8==1)
                const float i0 = frcp(fmaxf(z0, 0.1f));
                const float i1 = frcp(fmaxf(z1, 0.1f));
                const float g0 = (z0 > 0.1f) ? 1.f : ((z0 == 0.1f) ? 0.5f : 0.f);
                const float g1 = (z1 > 0.1f) ? 1.f : ((z1 == 0.1f) ? 0.5f : 0.f);
                const u64 invz = pk2(i0, i1);
                const u64 gz   = pk2(g0, g1);
                const u64 u  = f2mul(ph0, invz);
                const u64 v  = f2mul(ph1, invz);
                // (u - U)*wu : exact reference rounding
                const u64 ru = f2mul(f2fma(UU, M1, u), WU);
                const u64 rv = f2mul(f2fma(VV, M1, v), WV);
                const u64 su = f2mul(WU, invz);
                const u64 sv = f2mul(WV, invz);
                const u64 ug = f2mul(u, gz);
                const u64 vg = f2mul(v, gz);
                const u64 Ju0 = f2mul(FX, su);
                const u64 Jv1 = f2mul(FY, sv);
                const u64 Ju2 = f2mul(f2fma(ug, M1, CX), su);
                const u64 Jv2 = f2mul(f2fma(vg, M1, CYK), sv);
                const u64 Ju3 = f2fma(Ju0, av, f2mul(Ju2, bv));
                const u64 Jv3 = f2mul(Jv2, bv);
                A0  = f2fma(Ju0, Ju0, A0);
                A2  = f2fma(Ju0, Ju2, A2);
                A3  = f2fma(Ju0, Ju3, A3);
                A4  = f2fma(Jv1, Jv1, A4);
                A5  = f2fma(Jv1, Jv2, A5);
                A6  = f2fma(Jv1, Jv3, A6);
                A7  = f2fma(Ju2, Ju2, f2fma(Jv2, Jv2, A7));
                A8  = f2fma(Ju2, Ju3, f2fma(Jv2, Jv3, A8));
                A9  = f2fma(Ju3, Ju3, f2fma(Jv3, Jv3, A9));
                A10 = f2fma(Ju0, ru, A10);
                A11 = f2fma(Jv1, rv, A11);
                A12 = f2fma(Ju2, ru, f2fma(Jv2, rv, A12));
                A13 = f2fma(Ju3, ru, f2fma(Jv3, rv, A13));
                A14 = f2fma(ru, ru, f2fma(rv, rv, A14));
            }
            // per-lane totals (lo+hi of each f32x2 accumulator)
            float l, h, s[15];
            unpk2(A14, l, h); s[14] = l + h;
            unpk2(A0,  l, h); s[0]  = l + h;
            unpk2(A2,  l, h); s[2]  = l + h;
            unpk2(A3,  l, h); s[3]  = l + h;
            unpk2(A4,  l, h); s[4]  = l + h;
            unpk2(A5,  l, h); s[5]  = l + h;
            unpk2(A6,  l, h); s[6]  = l + h;
            unpk2(A7,  l, h); s[7]  = l + h;
            unpk2(A8,  l, h); s[8]  = l + h;
            unpk2(A9,  l, h); s[9]  = l + h;
            unpk2(A10, l, h); s[10] = l + h;
            unpk2(A11, l, h); s[11] = l + h;
            unpk2(A12, l, h); s[12] = l + h;
            unpk2(A13, l, h); s[13] = l + h;
            // pair-packed butterfly: 7 u64s, 70 SHFL + 35 f2add
            u64 R[7];
            R[0] = pk2(s[14], s[0]);
            R[1] = pk2(s[2],  s[3]);
            R[2] = pk2(s[4],  s[5]);
            R[3] = pk2(s[6],  s[7]);
            R[4] = pk2(s[8],  s[9]);
            R[5] = pk2(s[10], s[11]);
            R[6] = pk2(s[12], s[13]);
#pragma unroll
            for (int o = 16; o > 0; o >>= 1) {
#pragma unroll
                for (int k = 0; k < 7; k++) {
                    float lo, hi; unpk2(R[k], lo, hi);
                    const u64 other = pk2(__shfl_xor_sync(0xffffffffu, lo, o),
                                          __shfl_xor_sync(0xffffffffu, hi, o));
                    R[k] = f2add(R[k], other);
                }
            }
            unpk2(R[0], t[14], t[0]);
            unpk2(R[1], t[2],  t[3]);
            unpk2(R[2], t[4],  t[5]);
            unpk2(R[3], t[6],  t[7]);
            unpk2(R[4], t[8],  t[9]);
            unpk2(R[5], t[10], t[11]);
            unpk2(R[6], t[12], t[13]);
            t[1] = 0.f;                                  // Ju1==Jv0==0 exactly
        } else {
            // general-K fallback (not taken for this dataset)
            float a[15];
#pragma unroll
            for (int k = 0; k < 15; k++) a[k] = 0.f;
#pragma unroll 1
            for (int p = 0; p < NPAIRS; p++) {
                const int j = tid + p * THREADS;
                const float4 a4 = sA[j];
                const float4 b4 = sB[j];
                const float2 c2 = sC[j];
                const float4 q4 = ub[j];
#pragma unroll
                for (int hlf = 0; hlf < 2; hlf++) {
                    const float X = hlf ? a4.y : a4.x;
                    const float Y = hlf ? a4.w : a4.z;
                    const float Z = hlf ? b4.y : b4.x;
                    const float wu = hlf ? b4.w : b4.z;
                    const float wv = hlf ? c2.y : c2.x;
                    const float Uu = hlf ? q4.z : q4.x;
                    const float Vv = hlf ? q4.w : q4.y;
                    const float p0 = fmaf(cy, X, fmaf(sy, Z, tx));
                    const float p1 = Y + ty;
                    const float p2 = fmaf(-sy, X, fmaf(cy, Z, tz));
                    const float avv = p2 - tz;
                    const float bvv = tx - p0;
                    const float ph0 = fmaf(Kr[0], p0, fmaf(Kr[1], p1, Kr[2] * p2));
                    const float ph1 = fmaf(Kr[3], p0, fmaf(Kr[4], p1, Kr[5] * p2));
                    const float ph2 = fmaf(Kr[6], p0, fmaf(Kr[7], p1, Kr[8] * p2));
                    const float zc  = fmaxf(ph2, 0.1f);
                    const float gz  = (ph2 > 0.1f) ? 1.f : ((ph2 == 0.1f) ? 0.5f : 0.f);
                    const float invz = 1.0f / zc;
                    const float u = ph0 * invz;
                    const float v = ph1 * invz;
                    const float ru = (u - Uu) * wu;
                    const float rv = (v - Vv) * wv;
                    const float d0y = fmaf(Kr[0], avv, Kr[2] * bvv);
                    const float d1y = fmaf(Kr[3], avv, Kr[5] * bvv);
                    const float d2y = fmaf(Kr[6], avv, Kr[8] * bvv);
                    const float su_ = wu * invz;
                    const float sv_ = wv * invz;
                    const float ug = u * gz;
                    const float vg = v * gz;
                    const float Ju0 = fmaf(-ug, Kr[6], Kr[0]) * su_;
                    const float Ju1 = fmaf(-ug, Kr[7], Kr[1]) * su_;
                    const float Ju2 = fmaf(-ug, Kr[8], Kr[2]) * su_;
                    const float Ju3 = fmaf(-ug, d2y,  d0y ) * su_;
                    const float Jv0 = fmaf(-vg, Kr[6], Kr[3]) * sv_;
                    const float Jv1 = fmaf(-vg, Kr[7], Kr[4]) * sv_;
                    const float Jv2 = fmaf(-vg, Kr[8], Kr[5]) * sv_;
                    const float Jv3 = fmaf(-vg, d2y,  d1y ) * sv_;
                    a[0] = fmaf(Ju0, Ju0, fmaf(Jv0, Jv0, a[0]));
                    a[1] = fmaf(Ju0, Ju1, fmaf(Jv0, Jv1, a[1]));
                    a[2] = fmaf(Ju0, Ju2, fmaf(Jv0, Jv2, a[2]));
                    a[3] = fmaf(Ju0, Ju3, fmaf(Jv0, Jv3, a[3]));
                    a[4] = fmaf(Ju1, Ju1, fmaf(Jv1, Jv1, a[4]));
                    a[5] = fmaf(Ju1, Ju2, fmaf(Jv1, Jv2, a[5]));
                    a[6] = fmaf(Ju1, Ju3, fmaf(Jv1, Jv3, a[6]));
                    a[7] = fmaf(Ju2, Ju2, fmaf(Jv2, Jv2, a[7]));
                    a[8] = fmaf(Ju2, Ju3, fmaf(Jv2, Jv3, a[8]));
                    a[9] = fmaf(Ju3, Ju3, fmaf(Jv3, Jv3, a[9]));
                    a[10] = fmaf(Ju0, ru, fmaf(Jv0, rv, a[10]));
                    a[11] = fmaf(Ju1, ru, fmaf(Jv1, rv, a[11]));
                    a[12] = fmaf(Ju2, ru, fmaf(Jv2, rv, a[12]));
                    a[13] = fmaf(Ju3, ru, fmaf(Jv3, rv, a[13]));
                    a[14] = fmaf(ru, ru, fmaf(rv, rv, a[14]));
                }
            }
#pragma unroll
            for (int k = 0; k < 15; k++) t[k] = wsum(a[k]);
        }
    };

    // ---- initial pass at pose_init ----
    do_pass();
#pragma unroll
    for (int k = 0; k < 10; k++) jt[k] = t[k];
#pragma unroll
    for (int k = 0; k < 4; k++) gr[k] = t[10 + k];
    cst = 0.5f * t[14];

    float stepv[4], pn[4], dval[4];

    // ---- LM iterations ----
    for (int it = 0; it < NUM_ITER; it++) {
        {
            float A[4][4], bvec[4], xx[4];
            A[0][0] = jt[0]; A[0][1] = jt[1]; A[0][2] = jt[2]; A[0][3] = jt[3];
            A[1][0] = jt[1]; A[1][1] = jt[4]; A[1][2] = jt[5]; A[1][3] = jt[6];
            A[2][0] = jt[2]; A[2][1] = jt[5]; A[2][2] = jt[7]; A[2][3] = jt[8];
            A[3][0] = jt[3]; A[3][1] = jt[6]; A[3][2] = jt[8]; A[3][3] = jt[9];
            const float dg[4] = {jt[0], jt[4], jt[7], jt[9]};
            const float irad = frcp(radius);
#pragma unroll
            for (int i = 0; i < 4; i++) {
                const float d = fminf(fmaxf(dg[i], 1e-6f), 1e32f);
                dval[i] = d * irad;           // LM damping added to diagonal
                A[i][i] += dval[i];
                bvec[i] = gr[i];
            }
            solve4f(A, bvec, xx);
#pragma unroll
            for (int i = 0; i < 4; i++) {
                stepv[i] = -xx[i];
                pn[i] = pose[i] + stepv[i];
            }
        }
        cy = __cosf(pn[3]);
        sy = __sinf(pn[3]);
        tx = pn[0]; ty = pn[1]; tz = pn[2];

        do_pass();

        const float cn = 0.5f * t[14];
        // mcc = -s.(g + 0.5*jtj*s) == 0.5*(s'Ds - s.g)  [(jtj+D)s = -g]
        float sDs = 0.f, sg = 0.f;
#pragma unroll
        for (int i = 0; i < 4; i++) {
            sDs = fmaf(dval[i] * stepv[i], stepv[i], sDs);
            sg  = fmaf(stepv[i], gr[i], sg);
        }
        const float mcc = 0.5f * (sDs - sg);
        const float rel = (cst - cn) * frcp(mcc);
        const bool succ = (rel >= 1e-3f) && (mcc > 0.0f);
        if (succ) {
            const float tmp = 2.f * rel - 1.f;
            const float den = fmaxf(1.f - tmp * tmp * tmp, 1.f / 3.f);
            radius = fminf(radius * frcp(den), 1e16f);
            dec = 2.f;
#pragma unroll
            for (int k = 0; k < 10; k++) jt[k] = t[k];
#pragma unroll
            for (int k = 0; k < 4; k++) gr[k] = t[10 + k];
            cst = cn;
#pragma unroll
            for (int k = 0; k < 4; k++) pose[k] = pn[k];
        } else {
            radius = radius * frcp(dec);   // dec = 2^k: frcp exact
            dec *= 2.f;
            // next pass must run at the accepted pose again
            cy = __cosf(pose[3]);
            sy = __sinf(pose[3]);
            tx = pose[0]; ty = pose[1]; tz = pose[2];
        }
    }

    // ---- outputs + GN step (reuses carried jtj/grad) ----
    if (tid == 0) {
        float* __restrict__ out_pose = out + (size_t)b * 4;
        float* __restrict__ out_cost = out + (size_t)4 * B + b;
        float* __restrict__ out_plus = out + (size_t)5 * B + (size_t)b * 4;
#pragma unroll
        for (int k = 0; k < 4; k++) out_pose[k] = pose[k];
        *out_cost = cst;

        float A[4][4], bvec[4], xx[4];
        A[0][0] = jt[0]; A[0][1] = jt[1]; A[0][2] = jt[2]; A[0][3] = jt[3];
        A[1][0] = jt[1]; A[1][1] = jt[4]; A[1][2] = jt[5]; A[1][3] = jt[6];
        A[2][0] = jt[2]; A[2][1] = jt[5]; A[2][2] = jt[7]; A[2][3] = jt[8];
        A[3][0] = jt[3]; A[3][1] = jt[6]; A[3][2] = jt[8]; A[3][3] = jt[9];
#pragma unroll
        for (int i = 0; i < 4; i++) {
            A[i][i] += 1e-5f;          // EPS * eye
            bvec[i] = gr[i];
        }
        solve4f(A, bvec, xx);
#pragma unroll
        for (int k = 0; k < 4; k++)
            out_plus[k] = pose[k] - xx[k];
    }
}

extern "C" void kernel_launch(void* const* d_in, const int* in_sizes, int n_in,
                              void* d_out, int out_size) {
    const float* x3d       = (const float*)d_in[0];
    const float* x2d       = (const float*)d_in[1];
    const float* w2d       = (const float*)d_in[2];
    const float* pose_init = (const float*)d_in[3];
    const float* cam_mats  = (const float*)d_in[4];
    const int B = in_sizes[3] / 4;
    float* out = (float*)d_out;
    lm_kernel<<<B, THREADS>>>(x3d, x2d, w2d, pose_init, cam_mats, out, B);
}

// round 17
// speedup vs baseline: 1.1232x; 1.1232x over previous
#include <cuda_runtime.h>

// LM pose solver: B=4096 batches, N=512 points, DOF=4 (tx,ty,tz,yaw).
// One 32-thread CTA (single warp) per batch; 8 packed f32x2 point-pairs per
// lane. Pinhole-K fast path (exact zeros -> bit-identical to general form).
// REVERT to the measured-best 67.3us structure (smem-staged x2d/NUW, scalar
// butterfly, frcp bookkeeping, bounds(32,15)) + ONE change: decision-gated
// reduction. The accept test needs only the cost sum + old grad, so the
// 13-value jtj/grad butterfly (~130 slots) runs only on ACCEPTED steps.
// Warp-uniform branch (all lanes identical) -> no divergence.

#define NPTS     512
#define NPAIRS_T 256                     // total float2 pairs
#define THREADS  32
#define NPAIRS   (NPAIRS_T / THREADS)    // 8 pairs per lane
#define NUM_ITER 10

typedef unsigned long long u64;

__device__ __forceinline__ u64 pk2(float lo, float hi) {
    u64 r; asm("mov.b64 %0,{%1,%2};" : "=l"(r) : "f"(lo), "f"(hi)); return r;
}
__device__ __forceinline__ u64 pkb(float s) { return pk2(s, s); }
__device__ __forceinline__ void unpk2(u64 a, float& lo, float& hi) {
    asm("mov.b64 {%0,%1},%2;" : "=f"(lo), "=f"(hi) : "l"(a));
}
__device__ __forceinline__ u64 f2fma(u64 a, u64 b, u64 c) {
    u64 d; asm("fma.rn.f32x2 %0,%1,%2,%3;" : "=l"(d) : "l"(a), "l"(b), "l"(c)); return d;
}
__device__ __forceinline__ u64 f2mul(u64 a, u64 b) {
    u64 d; asm("mul.rn.f32x2 %0,%1,%2;" : "=l"(d) : "l"(a), "l"(b)); return d;
}
__device__ __forceinline__ u64 f2add(u64 a, u64 b) {
    u64 d; asm("add.rn.f32x2 %0,%1,%2;" : "=l"(d) : "l"(a), "l"(b)); return d;
}
__device__ __forceinline__ float frcp(float x) {
    float r; asm("rcp.approx.f32 %0, %1;" : "=f"(r) : "f"(x)); return r;
}
// warp butterfly sum (all lanes get total)
__device__ __forceinline__ float wsum(float x) {
#pragma unroll
    for (int o = 16; o > 0; o >>= 1)
        x += __shfl_xor_sync(0xffffffffu, x, o);
    return x;
}

// fp32 Gaussian elimination, no pivoting (A is SPD + LM damping).
// All reciprocals via rcp.approx (error ~1ulp*few, far inside 1e-3 budget).
__device__ __forceinline__ void solve4f(float A[4][4], float bv[4], float x[4]) {
#pragma unroll
    for (int k = 0; k < 4; k++) {
        const float inv = frcp(A[k][k]);
#pragma unroll
        for (int i = 0; i < 4; i++) {
            if (i > k) {
                const float f = A[i][k] * inv;
#pragma unroll
                for (int j = 0; j < 4; j++)
                    if (j >= k) A[i][j] = fmaf(-f, A[k][j], A[i][j]);
                bv[i] = fmaf(-f, bv[k], bv[i]);
            }
        }
    }
#pragma unroll
    for (int k = 3; k >= 0; k--) {
        float s = bv[k];
#pragma unroll
        for (int j = 0; j < 4; j++)
            if (j > k) s = fmaf(-A[k][j], x[j], s);
        x[k] = s * frcp(A[k][k]);
    }
}

__global__ void __launch_bounds__(THREADS, 15) lm_kernel(
    const float* __restrict__ x3d,
    const float* __restrict__ x2d,
    const float* __restrict__ w2d,
    const float* __restrict__ pose_init,
    const float* __restrict__ cam,
    float* __restrict__ out,   // [4B pose | B cost | 4B pose_plus]
    int B)
{
    // pair-packed layout: one pair (2 points) = sA.xyzw=(X0,X1,Y0,Y1),
    // sB=(Z0,Z1,WU0,WU1), sC=(WV0,WV1,NUW0,NUW1), sD=(NVW0,NVW1)
    __shared__ float4 sA[NPAIRS_T], sB[NPAIRS_T], sC[NPAIRS_T];
    __shared__ float2 sD[NPAIRS_T];

    const int b   = blockIdx.x;
    const int tid = threadIdx.x;

    // ---- stage point data (one-time) ----
    const float*  __restrict__ xb = x3d + (size_t)b * NPTS * 3;
    const float2* __restrict__ ub = (const float2*)(x2d + (size_t)b * NPTS * 2);
    const float2* __restrict__ wb = (const float2*)(w2d + (size_t)b * NPTS * 2);
    for (int j = tid; j < NPAIRS_T; j += THREADS) {
        const float X0 = xb[6*j+0], Y0 = xb[6*j+1], Z0 = xb[6*j+2];
        const float X1 = xb[6*j+3], Y1 = xb[6*j+4], Z1 = xb[6*j+5];
        const float2 u0 = ub[2*j], u1 = ub[2*j+1];
        const float2 w0 = wb[2*j], w1 = wb[2*j+1];
        sA[j] = make_float4(X0, X1, Y0, Y1);
        sB[j] = make_float4(Z0, Z1, w0.x, w1.x);
        sC[j] = make_float4(w0.y, w1.y, -(u0.x*w0.x), -(u1.x*w1.x));
        sD[j] = make_float2(-(u0.y*w0.y), -(u1.y*w1.y));
    }

    float Kr[9];
#pragma unroll
    for (int k = 0; k < 9; k++) Kr[k] = cam[(size_t)b * 9 + k];
    // Pinhole check: with exact zeros the specialized math is BIT-IDENTICAL
    // to the general formula (fmaf(x,0,y)==y exactly).
    const bool pin = (Kr[1] == 0.f) && (Kr[3] == 0.f) && (Kr[6] == 0.f) &&
                     (Kr[7] == 0.f) && (Kr[8] == 1.f);

    float pose[4];
#pragma unroll
    for (int k = 0; k < 4; k++) pose[k] = pose_init[b * 4 + k];
    float jt[10], gr[4];
    float cst = 0.f, radius = 30.0f, dec = 2.0f;

    float cy = __cosf(pose[3]);
    float sy = __sinf(pose[3]);
    float tx = pose[0], ty = pose[1], tz = pose[2];

    __syncwarp();   // staging visible warp-wide

    float t[15];     // reduced (warp-total) sums
    float sarr[14];  // per-lane partial sums (indices 0..13), reduced lazily

    // One fused residual+jacobian reduction pass at (tx,ty,tz,cy,sy).
    // On exit: t[14] (=2*cost) is warp-reduced in every lane; sarr[0..13]
    // holds the per-lane PARTIAL sums -- reduce_rest() finishes them.
    auto do_pass = [&]() {
        if (pin) {
            const float fx = Kr[0], cx = Kr[2], fy = Kr[4], cyk = Kr[5];
            u64 A0 = 0, A2 = 0, A3 = 0, A4 = 0, A5 = 0, A6 = 0, A7 = 0,
                A8 = 0, A9 = 0, A10 = 0, A11 = 0, A12 = 0, A13 = 0, A14 = 0;
            const u64 TX = pkb(tx), TY = pkb(ty), TZ = pkb(tz), nTZ = pkb(-tz);
            const u64 CYr = pkb(cy), SYr = pkb(sy), nSY = pkb(-sy);
            const u64 FX = pkb(fx), CX = pkb(cx), FY = pkb(fy), CYK = pkb(cyk);
            const u64 M1 = pkb(-1.0f);
#pragma unroll
            for (int p = 0; p < NPAIRS; p++) {
                const int j = tid + p * THREADS;
                const float4 a4 = sA[j];
                const float4 b4 = sB[j];
                const float4 c4 = sC[j];
                const float2 d2 = sD[j];
                const u64 Px = pk2(a4.x, a4.y), Py = pk2(a4.z, a4.w);
                const u64 Pz = pk2(b4.x, b4.y), WU = pk2(b4.z, b4.w);
                const u64 WV = pk2(c4.x, c4.y), NUW = pk2(c4.z, c4.w);
                const u64 NVW = pk2(d2.x, d2.y);
                const u64 p0 = f2fma(CYr, Px, f2fma(SYr, Pz, TX));
                const u64 p1 = f2add(Py, TY);
                const u64 p2 = f2fma(nSY, Px, f2fma(CYr, Pz, TZ));
                const u64 av = f2add(p2, nTZ);          //  -s*X + c*Z
                const u64 bv = f2fma(p0, M1, TX);       // -(c*X + s*Z)
                const u64 ph0 = f2fma(FX, p0, f2mul(CX, p2));
                const u64 ph1 = f2fma(FY, p1, f2mul(CYK, p2));
                float z0, z1; unpk2(p2, z0, z1);        // ph2 == p2 (K8==1)
                const float i0 = frcp(fmaxf(z0, 0.1f));
                const float i1 = frcp(fmaxf(z1, 0.1f));
                const float g0 = (z0 > 0.1f) ? 1.f : ((z0 == 0.1f) ? 0.5f : 0.f);
                const float g1 = (z1 > 0.1f) ? 1.f : ((z1 == 0.1f) ? 0.5f : 0.f);
                const u64 invz = pk2(i0, i1);
                const u64 gz   = pk2(g0, g1);
                const u64 u  = f2mul(ph0, invz);
                const u64 v  = f2mul(ph1, invz);
                const u64 ru = f2fma(u, WU, NUW);       // u*wu - x2d_u*wu
                const u64 rv = f2fma(v, WV, NVW);
                const u64 su = f2mul(WU, invz);
                const u64 sv = f2mul(WV, invz);
                const u64 ug = f2mul(u, gz);
                const u64 vg = f2mul(v, gz);
                const u64 Ju0 = f2mul(FX, su);
                const u64 Jv1 = f2mul(FY, sv);
                const u64 Ju2 = f2mul(f2fma(ug, M1, CX), su);
                const u64 Jv2 = f2mul(f2fma(vg, M1, CYK), sv);
                const u64 Ju3 = f2fma(Ju0, av, f2mul(Ju2, bv));
                const u64 Jv3 = f2mul(Jv2, bv);
                A0  = f2fma(Ju0, Ju0, A0);
                A2  = f2fma(Ju0, Ju2, A2);
                A3  = f2fma(Ju0, Ju3, A3);
                A4  = f2fma(Jv1, Jv1, A4);
                A5  = f2fma(Jv1, Jv2, A5);
                A6  = f2fma(Jv1, Jv3, A6);
                A7  = f2fma(Ju2, Ju2, f2fma(Jv2, Jv2, A7));
                A8  = f2fma(Ju2, Ju3, f2fma(Jv2, Jv3, A8));
                A9  = f2fma(Ju3, Ju3, f2fma(Jv3, Jv3, A9));
                A10 = f2fma(Ju0, ru, A10);
                A11 = f2fma(Jv1, rv, A11);
                A12 = f2fma(Ju2, ru, f2fma(Jv2, rv, A12));
                A13 = f2fma(Ju3, ru, f2fma(Jv3, rv, A13));
                A14 = f2fma(ru, ru, f2fma(rv, rv, A14));
            }
            float l, h;
            // cost reduced immediately: the accept decision needs only this
            unpk2(A14, l, h); t[14] = wsum(l + h);
            unpk2(A0,  l, h); sarr[0]  = l + h;
            sarr[1] = 0.f;                               // Ju1==Jv0==0 exactly
            unpk2(A2,  l, h); sarr[2]  = l + h;
            unpk2(A3,  l, h); sarr[3]  = l + h;
            unpk2(A4,  l, h); sarr[4]  = l + h;
            unpk2(A5,  l, h); sarr[5]  = l + h;
            unpk2(A6,  l, h); sarr[6]  = l + h;
            unpk2(A7,  l, h); sarr[7]  = l + h;
            unpk2(A8,  l, h); sarr[8]  = l + h;
            unpk2(A9,  l, h); sarr[9]  = l + h;
            unpk2(A10, l, h); sarr[10] = l + h;
            unpk2(A11, l, h); sarr[11] = l + h;
            unpk2(A12, l, h); sarr[12] = l + h;
            unpk2(A13, l, h); sarr[13] = l + h;
        } else {
            // general-K fallback (not taken for this dataset)
            float a[15];
#pragma unroll
            for (int k = 0; k < 15; k++) a[k] = 0.f;
#pragma unroll 1
            for (int p = 0; p < NPAIRS; p++) {
                const int j = tid + p * THREADS;
                const float4 a4 = sA[j];
                const float4 b4 = sB[j];
                const float4 c4 = sC[j];
                const float2 d2 = sD[j];
#pragma unroll
                for (int hlf = 0; hlf < 2; hlf++) {
                    const float X = hlf ? a4.y : a4.x;
                    const float Y = hlf ? a4.w : a4.z;
                    const float Z = hlf ? b4.y : b4.x;
                    const float wu = hlf ? b4.w : b4.z;
                    const float wv = hlf ? c4.y : c4.x;
                    const float nuw = hlf ? c4.w : c4.z;
                    const float nvw = hlf ? d2.y : d2.x;
                    const float p0 = fmaf(cy, X, fmaf(sy, Z, tx));
                    const float p1 = Y + ty;
                    const float p2 = fmaf(-sy, X, fmaf(cy, Z, tz));
                    const float avv = p2 - tz;
                    const float bvv = tx - p0;
                    const float ph0 = fmaf(Kr[0], p0, fmaf(Kr[1], p1, Kr[2] * p2));
                    const float ph1 = fmaf(Kr[3], p0, fmaf(Kr[4], p1, Kr[5] * p2));
                    const float ph2 = fmaf(Kr[6], p0, fmaf(Kr[7], p1, Kr[8] * p2));
                    const float zc  = fmaxf(ph2, 0.1f);
                    const float gz  = (ph2 > 0.1f) ? 1.f : ((ph2 == 0.1f) ? 0.5f : 0.f);
                    const float invz = 1.0f / zc;
                    const float u = ph0 * invz;
                    const float v = ph1 * invz;
                    const float ru = fmaf(u, wu, nuw);
                    const float rv = fmaf(v, wv, nvw);
                    const float d0y = fmaf(Kr[0], avv, Kr[2] * bvv);
                    const float d1y = fmaf(Kr[3], avv, Kr[5] * bvv);
                    const float d2y = fmaf(Kr[6], avv, Kr[8] * bvv);
                    const float su_ = wu * invz;
                    const float sv_ = wv * invz;
                    const float ug = u * gz;
                    const float vg = v * gz;
                    const float Ju0 = fmaf(-ug, Kr[6], Kr[0]) * su_;
                    const float Ju1 = fmaf(-ug, Kr[7], Kr[1]) * su_;
                    const float Ju2 = fmaf(-ug, Kr[8], Kr[2]) * su_;
                    const float Ju3 = fmaf(-ug, d2y,  d0y ) * su_;
                    const float Jv0 = fmaf(-vg, Kr[6], Kr[3]) * sv_;
                    const float Jv1 = fmaf(-vg, Kr[7], Kr[4]) * sv_;
                    const float Jv2 = fmaf(-vg, Kr[8], Kr[5]) * sv_;
                    const float Jv3 = fmaf(-vg, d2y,  d1y ) * sv_;
                    a[0] = fmaf(Ju0, Ju0, fmaf(Jv0, Jv0, a[0]));
                    a[1] = fmaf(Ju0, Ju1, fmaf(Jv0, Jv1, a[1]));
                    a[2] = fmaf(Ju0, Ju2, fmaf(Jv0, Jv2, a[2]));
                    a[3] = fmaf(Ju0, Ju3, fmaf(Jv0, Jv3, a[3]));
                    a[4] = fmaf(Ju1, Ju1, fmaf(Jv1, Jv1, a[4]));
                    a[5] = fmaf(Ju1, Ju2, fmaf(Jv1, Jv2, a[5]));
                    a[6] = fmaf(Ju1, Ju3, fmaf(Jv1, Jv3, a[6]));
                    a[7] = fmaf(Ju2, Ju2, fmaf(Jv2, Jv2, a[7]));
                    a[8] = fmaf(Ju2, Ju3, fmaf(Jv2, Jv3, a[8]));
                    a[9] = fmaf(Ju3, Ju3, fmaf(Jv3, Jv3, a[9]));
                    a[10] = fmaf(Ju0, ru, fmaf(Jv0, rv, a[10]));
                    a[11] = fmaf(Ju1, ru, fmaf(Jv1, rv, a[11]));
                    a[12] = fmaf(Ju2, ru, fmaf(Jv2, rv, a[12]));
                    a[13] = fmaf(Ju3, ru, fmaf(Jv3, rv, a[13]));
                    a[14] = fmaf(ru, ru, fmaf(rv, rv, a[14]));
                }
            }
            t[14] = wsum(a[14]);
#pragma unroll
            for (int k = 0; k < 14; k++) sarr[k] = a[k];
        }
    };

    // Finish the deferred jtj/grad reduction (13 or 14 butterflies).
    auto reduce_rest = [&]() {
        t[0] = wsum(sarr[0]);
        t[1] = pin ? 0.f : wsum(sarr[1]);   // warp-uniform branch
#pragma unroll
        for (int k = 2; k < 14; k++) t[k] = wsum(sarr[k]);
    };

    // ---- initial pass at pose_init (always needs the full reduce) ----
    do_pass();
    reduce_rest();
#pragma unroll
    for (int k = 0; k < 10; k++) jt[k] = t[k];
#pragma unroll
    for (int k = 0; k < 4; k++) gr[k] = t[10 + k];
    cst = 0.5f * t[14];

    float stepv[4], pn[4], dval[4];

    // ---- LM iterations ----
    for (int it = 0; it < NUM_ITER; it++) {
        {
            float A[4][4], bvec[4], xx[4];
            A[0][0] = jt[0]; A[0][1] = jt[1]; A[0][2] = jt[2]; A[0][3] = jt[3];
            A[1][0] = jt[1]; A[1][1] = jt[4]; A[1][2] = jt[5]; A[1][3] = jt[6];
            A[2][0] = jt[2]; A[2][1] = jt[5]; A[2][2] = jt[7]; A[2][3] = jt[8];
            A[3][0] = jt[3]; A[3][1] = jt[6]; A[3][2] = jt[8]; A[3][3] = jt[9];
            const float dg[4] = {jt[0], jt[4], jt[7], jt[9]};
            const float irad = frcp(radius);
#pragma unroll
            for (int i = 0; i < 4; i++) {
                const float d = fminf(fmaxf(dg[i], 1e-6f), 1e32f);
                dval[i] = d * irad;           // LM damping added to diagonal
                A[i][i] += dval[i];
                bvec[i] = gr[i];
            }
            solve4f(A, bvec, xx);
#pragma unroll
            for (int i = 0; i < 4; i++) {
                stepv[i] = -xx[i];
                pn[i] = pose[i] + stepv[i];
            }
        }
        cy = __cosf(pn[3]);
        sy = __sinf(pn[3]);
        tx = pn[0]; ty = pn[1]; tz = pn[2];

        do_pass();                      // reduces ONLY the cost sum

        const float cn = 0.5f * t[14];
        // mcc = -s.(g + 0.5*jtj*s) == 0.5*(s'Ds - s.g)  [(jtj+D)s = -g]
        // uses OLD gr -- available before any further reduction.
        float sDs = 0.f, sg = 0.f;
#pragma unroll
        for (int i = 0; i < 4; i++) {
            sDs = fmaf(dval[i] * stepv[i], stepv[i], sDs);
            sg  = fmaf(stepv[i], gr[i], sg);
        }
        const float mcc = 0.5f * (sDs - sg);
        const float rel = (cst - cn) * frcp(mcc);
        const bool succ = (rel >= 1e-3f) && (mcc > 0.0f);
        if (succ) {
            // only now pay for the jtj/grad reduction
            reduce_rest();
            const float tmp = 2.f * rel - 1.f;
            const float den = fmaxf(1.f - tmp * tmp * tmp, 1.f / 3.f);
            radius = fminf(radius * frcp(den), 1e16f);
            dec = 2.f;
#pragma unroll
            for (int k = 0; k < 10; k++) jt[k] = t[k];
#pragma unroll
            for (int k = 0; k < 4; k++) gr[k] = t[10 + k];
            cst = cn;
#pragma unroll
            for (int k = 0; k < 4; k++) pose[k] = pn[k];
        } else {
            radius = radius * frcp(dec);   // dec = 2^k: frcp exact
            dec *= 2.f;
            // next pass must run at the accepted pose again
            cy = __cosf(pose[3]);
            sy = __sinf(pose[3]);
            tx = pose[0]; ty = pose[1]; tz = pose[2];
        }
    }

    // ---- outputs + GN step (reuses carried jtj/grad) ----
    if (tid == 0) {
        float* __restrict__ out_pose = out + (size_t)b * 4;
        float* __restrict__ out_cost = out + (size_t)4 * B + b;
        float* __restrict__ out_plus = out + (size_t)5 * B + (size_t)b * 4;
#pragma unroll
        for (int k = 0; k < 4; k++) out_pose[k] = pose[k];
        *out_cost = cst;

        float A[4][4], bvec[4], xx[4];
        A[0][0] = jt[0]; A[0][1] = jt[1]; A[0][2] = jt[2]; A[0][3] = jt[3];
        A[1][0] = jt[1]; A[1][1] = jt[4]; A[1][2] = jt[5]; A[1][3] = jt[6];
        A[2][0] = jt[2]; A[2][1] = jt[5]; A[2][2] = jt[7]; A[2][3] = jt[8];
        A[3][0] = jt[3]; A[3][1] = jt[6]; A[3][2] = jt[8]; A[3][3] = jt[9];
#pragma unroll
        for (int i = 0; i < 4; i++) {
            A[i][i] += 1e-5f;          // EPS * eye
            bvec[i] = gr[i];
        }
        solve4f(A, bvec, xx);
#pragma unroll
        for (int k = 0; k < 4; k++)
            out_plus[k] = pose[k] - xx[k];
    }
}

extern "C" void kernel_launch(void* const* d_in, const int* in_sizes, int n_in,
                              void* d_out, int out_size) {
    const float* x3d       = (const float*)d_in[0];
    const float* x2d       = (const float*)d_in[1];
    const float* w2d       = (const float*)d_in[2];
    const float* pose_init = (const float*)d_in[3];
    const float* cam_mats  = (const float*)d_in[4];
    const int B = in_sizes[3] / 4;
    float* out = (float*)d_out;
    lm_kernel<<<B, THREADS>>>(x3d, x2d, w2d, pose_init, cam_mats, out, B);
}